// round 15
// baseline (speedup 1.0000x reference)
#include <cuda_runtime.h>
#include <cuda_bf16.h>
#include <math.h>
#include <stdint.h>

// Problem constants
#define CP_B      4
#define CP_L      8192
#define CP_D      1024
#define CP_K      2
#define CP_NF     16
#define CP_E      64              // K * 2 * NF
#define CP_BL     (CP_B * CP_L)   // 32768 tokens
#define CP_CHUNK  512
#define CP_NCHUNK (CP_L / CP_CHUNK)        // 16
#define CP_NCHTOT (CP_BL / CP_CHUNK)       // 64

// Scratch (static device globals)
__device__ float4 g_gates[CP_BL];
__device__ float4 g_scan[CP_BL];
__device__ float4 g_agg[CP_NCHTOT];
__device__ float2 g_pre[CP_NCHTOT];
__device__ int    g_sync;                                   // zero-initialized
__device__ __align__(16) __nv_bfloat16 g_Bhi[CP_D * CP_E];  // [n][k], K-major 128B rows
__device__ __align__(16) __nv_bfloat16 g_Blo[CP_D * CP_E];

__device__ __forceinline__ float4 comb(float4 l, float4 r) {
    float4 o;
    o.x = r.x * l.x;  o.y = fmaf(r.x, l.y, r.y);
    o.z = r.z * l.z;  o.w = fmaf(r.z, l.w, r.w);
    return o;
}

// ---------------- helpers (sm_103 base-target only: no tcgen05) ----------------
__device__ __forceinline__ uint32_t smem_u32(const void* p) {
    uint32_t a;
    asm("{ .reg .u64 t; cvta.to.shared.u64 t, %1; cvt.u32.u64 %0, t; }" : "=r"(a) : "l"(p));
    return a;
}
__device__ __forceinline__ uint32_t swz(uint32_t off) {   // SW128 swizzle (128B rows)
    return off ^ ((off >> 3) & 0x70);
}
__device__ __forceinline__ void ldsm4(uint32_t& r0, uint32_t& r1, uint32_t& r2, uint32_t& r3,
                                      uint32_t addr) {
    asm volatile("ldmatrix.sync.aligned.m8n8.x4.shared.b16 {%0,%1,%2,%3}, [%4];"
                 : "=r"(r0), "=r"(r1), "=r"(r2), "=r"(r3) : "r"(addr));
}
__device__ __forceinline__ void mma16816(float* c, const uint32_t* a, uint32_t b0, uint32_t b1) {
    asm volatile("mma.sync.aligned.m16n8k16.row.col.f32.bf16.bf16.f32 "
                 "{%0,%1,%2,%3}, {%4,%5,%6,%7}, {%8,%9}, {%0,%1,%2,%3};"
                 : "+f"(c[0]), "+f"(c[1]), "+f"(c[2]), "+f"(c[3])
                 : "r"(a[0]), "r"(a[1]), "r"(a[2]), "r"(a[3]), "r"(b0), "r"(b1));
}
__device__ __forceinline__ void cp16(uint32_t dst, const void* src) {
    asm volatile("cp.async.ca.shared.global [%0], [%1], 16;" :: "r"(dst), "l"(src));
}
__device__ __forceinline__ void cp_commit() {
    asm volatile("cp.async.commit_group;" ::: "memory");
}
template <int N>
__device__ __forceinline__ void cp_wait() {
    asm volatile("cp.async.wait_group %0;" :: "n"(N) : "memory");
}

// ---------------------------------------------------------------------------
// Kernel 1: gate projections (+ fused read_w hi/lo split). R12 form.
// 2048 blocks x 256 threads; warp = 2 tokens.
// ---------------------------------------------------------------------------
__global__ __launch_bounds__(256) void gates_kernel(
    const float* __restrict__ x,
    const float* __restrict__ inc_w, const float* __restrict__ inc_b,
    const float* __restrict__ reset_w, const float* __restrict__ reset_b,
    const float* __restrict__ read_w,
    float* __restrict__ out_inc_logits)
{
    __shared__ __align__(16) float sI0[CP_D], sI1[CP_D], sR0[CP_D], sR1[CP_D];
    int tid = threadIdx.x;

    // ---- fused prep: this block's 32 elements of read_w hi/lo split ----
    if (tid < 32) {
        int idx = blockIdx.x * 32 + tid;    // 0..65535
        int n = idx >> 6, k = idx & 63;
        float v = read_w[k * CP_D + n];
        __nv_bfloat16 h = __float2bfloat16(v);
        float res = v - __bfloat162float(h);
        g_Bhi[n * CP_E + k] = h;
        g_Blo[n * CP_E + k] = __float2bfloat16(res);
    }

    for (int d = tid; d < CP_D; d += 256) {
        sI0[d] = inc_w[2 * d];     sI1[d] = inc_w[2 * d + 1];
        sR0[d] = reset_w[2 * d];   sR1[d] = reset_w[2 * d + 1];
    }
    __syncthreads();

    int lane = tid & 31;
    int wid  = tid >> 5;
    int tokA = blockIdx.x * 16 + wid * 2;
    int tokB = tokA + 1;

    const float4* xA = reinterpret_cast<const float4*>(x + (size_t)tokA * CP_D);
    const float4* xB = reinterpret_cast<const float4*>(x + (size_t)tokB * CP_D);
    const float4* wI0 = reinterpret_cast<const float4*>(sI0);
    const float4* wI1 = reinterpret_cast<const float4*>(sI1);
    const float4* wR0 = reinterpret_cast<const float4*>(sR0);
    const float4* wR1 = reinterpret_cast<const float4*>(sR1);

    float a0 = 0.f, a1 = 0.f, a2 = 0.f, a3 = 0.f;
    float b0 = 0.f, b1 = 0.f, b2 = 0.f, b3 = 0.f;
#pragma unroll
    for (int i = 0; i < 8; ++i) {
        int i4 = lane + (i << 5);
        float4 xa = __ldcs(&xA[i4]);
        float4 xb = __ldcs(&xB[i4]);
        float4 u = wI0[i4], v = wI1[i4], p = wR0[i4], q = wR1[i4];
        a0 = fmaf(xa.x, u.x, a0); a0 = fmaf(xa.y, u.y, a0);
        a0 = fmaf(xa.z, u.z, a0); a0 = fmaf(xa.w, u.w, a0);
        a1 = fmaf(xa.x, v.x, a1); a1 = fmaf(xa.y, v.y, a1);
        a1 = fmaf(xa.z, v.z, a1); a1 = fmaf(xa.w, v.w, a1);
        a2 = fmaf(xa.x, p.x, a2); a2 = fmaf(xa.y, p.y, a2);
        a2 = fmaf(xa.z, p.z, a2); a2 = fmaf(xa.w, p.w, a2);
        a3 = fmaf(xa.x, q.x, a3); a3 = fmaf(xa.y, q.y, a3);
        a3 = fmaf(xa.z, q.z, a3); a3 = fmaf(xa.w, q.w, a3);
        b0 = fmaf(xb.x, u.x, b0); b0 = fmaf(xb.y, u.y, b0);
        b0 = fmaf(xb.z, u.z, b0); b0 = fmaf(xb.w, u.w, b0);
        b1 = fmaf(xb.x, v.x, b1); b1 = fmaf(xb.y, v.y, b1);
        b1 = fmaf(xb.z, v.z, b1); b1 = fmaf(xb.w, v.w, b1);
        b2 = fmaf(xb.x, p.x, b2); b2 = fmaf(xb.y, p.y, b2);
        b2 = fmaf(xb.z, p.z, b2); b2 = fmaf(xb.w, p.w, b2);
        b3 = fmaf(xb.x, q.x, b3); b3 = fmaf(xb.y, q.y, b3);
        b3 = fmaf(xb.z, q.z, b3); b3 = fmaf(xb.w, q.w, b3);
    }
#pragma unroll
    for (int off = 16; off > 0; off >>= 1) {
        a0 += __shfl_xor_sync(0xffffffffu, a0, off);
        a1 += __shfl_xor_sync(0xffffffffu, a1, off);
        a2 += __shfl_xor_sync(0xffffffffu, a2, off);
        a3 += __shfl_xor_sync(0xffffffffu, a3, off);
        b0 += __shfl_xor_sync(0xffffffffu, b0, off);
        b1 += __shfl_xor_sync(0xffffffffu, b1, off);
        b2 += __shfl_xor_sync(0xffffffffu, b2, off);
        b3 += __shfl_xor_sync(0xffffffffu, b3, off);
    }
    if (lane == 0) {
        float ib0 = inc_b[0], ib1 = inc_b[1], rb0 = reset_b[0], rb1 = reset_b[1];
        float ilA0 = a0 + ib0, ilA1 = a1 + ib1;
        float rlA0 = a2 + rb0, rlA1 = a3 + rb1;
        reinterpret_cast<float2*>(out_inc_logits)[tokA] = make_float2(ilA0, ilA1);
        g_gates[tokA] = make_float4(1.f / (1.f + expf(rlA0)),
                                    1.f / (1.f + expf(-ilA0)),
                                    1.f / (1.f + expf(rlA1)),
                                    1.f / (1.f + expf(-ilA1)));
        float ilB0 = b0 + ib0, ilB1 = b1 + ib1;
        float rlB0 = b2 + rb0, rlB1 = b3 + rb1;
        reinterpret_cast<float2*>(out_inc_logits)[tokB] = make_float2(ilB0, ilB1);
        g_gates[tokB] = make_float4(1.f / (1.f + expf(rlB0)),
                                    1.f / (1.f + expf(-ilB0)),
                                    1.f / (1.f + expf(rlB1)),
                                    1.f / (1.f + expf(-ilB1)));
    }
}

// ---------------------------------------------------------------------------
// Kernel 2: per-chunk inclusive scan + fused aggregate scan in the tail.
// ---------------------------------------------------------------------------
__global__ __launch_bounds__(256) void chunkscan_kernel()
{
    __shared__ float4 wagg[8];
    __shared__ float4 wexc[8];
    __shared__ int s_last;
    int t = threadIdx.x, lane = t & 31, wid = t >> 5;
    int tok = blockIdx.x * CP_CHUNK + 2 * t;

    float4 a = g_gates[tok];
    float4 b = g_gates[tok + 1];
    float4 s = comb(a, b);

#pragma unroll
    for (int off = 1; off < 32; off <<= 1) {
        float4 l;
        l.x = __shfl_up_sync(0xffffffffu, s.x, off);
        l.y = __shfl_up_sync(0xffffffffu, s.y, off);
        l.z = __shfl_up_sync(0xffffffffu, s.z, off);
        l.w = __shfl_up_sync(0xffffffffu, s.w, off);
        if (lane >= off) s = comb(l, s);
    }
    if (lane == 31) wagg[wid] = s;
    __syncthreads();

    if (wid == 0) {
        float4 v = (lane < 8) ? wagg[lane] : make_float4(1.f, 0.f, 1.f, 0.f);
#pragma unroll
        for (int off = 1; off < 8; off <<= 1) {
            float4 l;
            l.x = __shfl_up_sync(0xffffffffu, v.x, off);
            l.y = __shfl_up_sync(0xffffffffu, v.y, off);
            l.z = __shfl_up_sync(0xffffffffu, v.z, off);
            l.w = __shfl_up_sync(0xffffffffu, v.w, off);
            if (lane >= off && lane < 8) v = comb(l, v);
        }
        if (lane == 0) wexc[0] = make_float4(1.f, 0.f, 1.f, 0.f);
        if (lane < 7)  wexc[lane + 1] = v;
    }
    __syncthreads();

    float4 se;
    {
        float4 l;
        l.x = __shfl_up_sync(0xffffffffu, s.x, 1);
        l.y = __shfl_up_sync(0xffffffffu, s.y, 1);
        l.z = __shfl_up_sync(0xffffffffu, s.z, 1);
        l.w = __shfl_up_sync(0xffffffffu, s.w, 1);
        se = (lane == 0) ? make_float4(1.f, 0.f, 1.f, 0.f) : l;
    }
    float4 P = comb(wexc[wid], se);
    float4 o0 = comb(P, a);
    float4 o1 = comb(o0, b);
    g_scan[tok]     = o0;
    g_scan[tok + 1] = o1;
    if (t == 255) g_agg[blockIdx.x] = o1;

    __threadfence();
    __syncthreads();
    if (t == 0) {
        int prev = atomicAdd(&g_sync, 1);
        s_last = (prev == CP_NCHTOT - 1);
    }
    __syncthreads();
    if (s_last) {
        if (t < CP_B) {
            float c0 = 0.f, c1 = 0.f;
            for (int j = 0; j < CP_NCHUNK; ++j) {
                g_pre[t * CP_NCHUNK + j] = make_float2(c0, c1);
                float4 ag = g_agg[t * CP_NCHUNK + j];
                c0 = fmaf(ag.x, c0, ag.y);
                c1 = fmaf(ag.z, c1, ag.w);
            }
        }
        if (t == 0) g_sync = 0;
    }
}

// ---------------------------------------------------------------------------
// Kernel 3: counters + embedding + mma.sync bf16x3 GEMM + bias.
// Epilogue routed through per-warp smem scratch -> coalesced STG.128
// (8x fewer global-store line visits). Mainloop identical to R12/R9.
// ---------------------------------------------------------------------------
#define SMB_BIAS  0
#define SMB_EHI   4096
#define SMB_ELO   20480
#define SMB_B     36864
#define SMB_BUF   16384
#define SMB_SCR   (SMB_B + 2 * SMB_BUF)   // 69632, per-warp 2KB scratch
#define SM_TOT    (SMB_SCR + 8 * 2048)    // 86016

__device__ __forceinline__ void stage_B(uint32_t sb, int nt, int buf, int tid)
{
    const char* srcH = (const char*)g_Bhi + (size_t)nt * 64 * 128;
    const char* srcL = (const char*)g_Blo + (size_t)nt * 64 * 128;
    uint32_t dstH = sb + SMB_B + buf * SMB_BUF;
    uint32_t dstL = dstH + 8192;
#pragma unroll
    for (int m = 0; m < 2; ++m) {
        int idx = tid + m * 256;          // 0..511
        int nl = idx >> 3, c16 = idx & 7;
        uint32_t sw = swz((uint32_t)(nl * 128 + c16 * 16));
        cp16(dstH + sw, srcH + nl * 128 + c16 * 16);
        cp16(dstL + sw, srcL + nl * 128 + c16 * 16);
    }
}

__global__ __launch_bounds__(256, 2) void readout_kernel(
    const float* __restrict__ read_b,
    float* __restrict__ out_inj,        // (B*L, 1024)
    float* __restrict__ out_counters)   // (B*L, 2)
{
    extern __shared__ __align__(1024) char smem[];
    uint32_t sb = smem_u32(smem);
    int tid = threadIdx.x, lane = tid & 31, w = tid >> 5;
    int wy = w >> 1, wx = w & 1;        // 4 m-groups x 2 n-groups
    int tok0 = blockIdx.x * 128;

    // bias -> smem
    reinterpret_cast<float4*>(smem + SMB_BIAS)[tid] =
        reinterpret_cast<const float4*>(read_b)[tid];

    // ---- counters + embedding -> bf16 hi/lo swizzled tiles [128 x 64] ----
    {
        int t   = tid >> 1;
        int k   = tid & 1;
        int tok = tok0 + t;
        int b   = tok / CP_L;
        int jc  = (tok % CP_L) / CP_CHUNK;
        float2 pre = g_pre[b * CP_NCHUNK + jc];
        float4 sc  = g_scan[tok];
        float pk = k ? sc.z : sc.x;
        float pi = k ? sc.w : sc.y;
        float pp = k ? pre.y : pre.x;
        float c  = fmaf(pk, pp, pi);
        out_counters[tok * 2 + k] = c;

        float sv[16], cv[16];
#pragma unroll
        for (int f = 0; f < CP_NF; ++f) {
            float invf = exp2f(-12.0f * (float)f / 15.0f);
            sincosf(c * invf, &sv[f], &cv[f]);
        }
#pragma unroll
        for (int q = 0; q < 8; ++q) {
            unsigned long long hi = 0ull, lo = 0ull;
#pragma unroll
            for (int bq = 0; bq < 4; ++bq) {
                int j = 4 * q + bq;
                float v = (j < 16) ? sv[j] : cv[j - 16];
                __nv_bfloat16 h = __float2bfloat16(v);
                float res = v - __bfloat162float(h);
                __nv_bfloat16 l = __float2bfloat16(res);
                hi |= (unsigned long long)__bfloat16_as_ushort(h) << (16 * bq);
                lo |= (unsigned long long)__bfloat16_as_ushort(l) << (16 * bq);
            }
            uint32_t off = (uint32_t)(t * 128 + k * 64 + q * 8);
            uint32_t sw = swz(off);
            *reinterpret_cast<unsigned long long*>(smem + SMB_EHI + sw) = hi;
            *reinterpret_cast<unsigned long long*>(smem + SMB_ELO + sw) = lo;
        }
    }

    // prefetch B chunk 0
    stage_B(sb, 0, 0, tid);
    cp_commit();

    __syncthreads();   // emb tiles complete (never modified again)

    int row = lane >> 2;
    int mlsb = lane >> 3, r8 = lane & 7;

    // ---- A fragments register-resident ----
    uint32_t ah[4][2][4], al[4][2][4];
#pragma unroll
    for (int kk = 0; kk < 4; ++kk)
#pragma unroll
        for (int mt = 0; mt < 2; ++mt) {
            uint32_t aoff = swz((uint32_t)((wy * 32 + mt * 16 + (mlsb & 1) * 8 + r8) * 128 +
                                           (2 * kk + (mlsb >> 1)) * 16));
            ldsm4(ah[kk][mt][0], ah[kk][mt][1], ah[kk][mt][2], ah[kk][mt][3],
                  sb + SMB_EHI + aoff);
            ldsm4(al[kk][mt][0], al[kk][mt][1], al[kk][mt][2], al[kk][mt][3],
                  sb + SMB_ELO + aoff);
        }

    uint32_t scr = sb + SMB_SCR + w * 2048;

#pragma unroll 1
    for (int nt = 0; nt < 16; ++nt) {
        int buf = nt & 1;
        if (nt < 15) {
            stage_B(sb, nt + 1, buf ^ 1, tid);
            cp_commit();
            cp_wait<1>();
        } else {
            cp_wait<0>();
        }
        __syncthreads();

        uint32_t bbase = sb + SMB_B + buf * SMB_BUF;
        float acc[2][4][4];
#pragma unroll
        for (int mt = 0; mt < 2; ++mt)
#pragma unroll
            for (int p = 0; p < 4; ++p)
#pragma unroll
                for (int q = 0; q < 4; ++q) acc[mt][p][q] = 0.f;

#pragma unroll
        for (int kk = 0; kk < 4; ++kk) {
#pragma unroll
            for (int p4 = 0; p4 < 2; ++p4) {
                int pg = wx * 2 + p4;
                uint32_t bh[4], bl[4];
                uint32_t boff = swz((uint32_t)((pg * 16 + (mlsb >> 1) * 8 + r8) * 128 +
                                               (2 * kk + (mlsb & 1)) * 16));
                ldsm4(bh[0], bh[1], bh[2], bh[3], bbase + boff);
                ldsm4(bl[0], bl[1], bl[2], bl[3], bbase + 8192 + boff);
#pragma unroll
                for (int mt = 0; mt < 2; ++mt) {
                    mma16816(acc[mt][2 * p4],     ah[kk][mt], bh[0], bh[1]);
                    mma16816(acc[mt][2 * p4 + 1], ah[kk][mt], bh[2], bh[3]);
                    mma16816(acc[mt][2 * p4],     ah[kk][mt], bl[0], bl[1]);
                    mma16816(acc[mt][2 * p4 + 1], ah[kk][mt], bl[2], bl[3]);
                    mma16816(acc[mt][2 * p4],     al[kk][mt], bh[0], bh[1]);
                    mma16816(acc[mt][2 * p4 + 1], al[kk][mt], bh[2], bh[3]);
                }
            }
        }

        // ---- epilogue: per-warp smem transpose -> coalesced STG.128 ----
        const float* sbias = reinterpret_cast<const float*>(smem + SMB_BIAS) +
                             nt * 64 + wx * 32;
        int t3 = lane & 3;
        int ch = lane & 7;
        float4 bv = *reinterpret_cast<const float4*>(sbias + ch * 4);
#pragma unroll
        for (int mt = 0; mt < 2; ++mt) {
            // scatter fragment into swizzled scratch (16 rows x 128B)
#pragma unroll
            for (int p = 0; p < 4; ++p) {
                int c16 = 2 * p + (t3 >> 1);
                uint32_t sw16 = (uint32_t)((c16 ^ (row & 7)) * 16 + (t3 & 1) * 8);
                uint32_t a0 = scr + (uint32_t)(row * 128) + sw16;
                uint32_t a1 = scr + (uint32_t)((row + 8) * 128) + sw16;
                asm volatile("st.shared.v2.f32 [%0], {%1, %2};"
                             :: "r"(a0), "f"(acc[mt][p][0]), "f"(acc[mt][p][1]));
                asm volatile("st.shared.v2.f32 [%0], {%1, %2};"
                             :: "r"(a1), "f"(acc[mt][p][2]), "f"(acc[mt][p][3]));
            }
            __syncwarp();
            // gather rows, add bias, coalesced streaming stores
#pragma unroll
            for (int i = 0; i < 4; ++i) {
                int lrow = i * 4 + (lane >> 3);
                uint32_t ra = scr + (uint32_t)(lrow * 128 + ((ch ^ (lrow & 7)) * 16));
                float4 vv;
                asm volatile("ld.shared.v4.f32 {%0,%1,%2,%3}, [%4];"
                             : "=f"(vv.x), "=f"(vv.y), "=f"(vv.z), "=f"(vv.w) : "r"(ra));
                vv.x += bv.x; vv.y += bv.y; vv.z += bv.z; vv.w += bv.w;
                float* o = out_inj + (size_t)(tok0 + wy * 32 + mt * 16 + lrow) * CP_D +
                           nt * 64 + wx * 32 + ch * 4;
                __stcs(reinterpret_cast<float4*>(o), vv);
            }
            __syncwarp();
        }
        __syncthreads();
    }
}

// ---------------------------------------------------------------------------
// Launch: THREE kernels.
// ---------------------------------------------------------------------------
extern "C" void kernel_launch(void* const* d_in, const int* in_sizes, int n_in,
                              void* d_out, int out_size)
{
    const float* x       = (const float*)d_in[0];
    const float* inc_w   = (const float*)d_in[1];
    const float* inc_b   = (const float*)d_in[2];
    const float* reset_w = (const float*)d_in[3];
    const float* reset_b = (const float*)d_in[4];
    const float* read_w  = (const float*)d_in[5];
    const float* read_b  = (const float*)d_in[6];

    float* out        = (float*)d_out;
    float* out_inj    = out;
    float* out_inclog = out + (size_t)CP_BL * CP_D;
    float* out_cnt    = out_inclog + (size_t)CP_BL * CP_K;

    cudaFuncSetAttribute(readout_kernel,
                         cudaFuncAttributeMaxDynamicSharedMemorySize, SM_TOT);

    gates_kernel<<<CP_BL / 16, 256>>>(x, inc_w, inc_b, reset_w, reset_b,
                                      read_w, out_inclog);
    chunkscan_kernel<<<CP_NCHTOT, 256>>>();
    readout_kernel<<<CP_BL / 128, 256, SM_TOT>>>(read_b, out_inj, out_cnt);
}

// round 16
// speedup vs baseline: 1.0447x; 1.0447x over previous
#include <cuda_runtime.h>
#include <cuda_bf16.h>
#include <math.h>
#include <stdint.h>

// Problem constants
#define CP_B      4
#define CP_L      8192
#define CP_D      1024
#define CP_K      2
#define CP_NF     16
#define CP_E      64              // K * 2 * NF
#define CP_BL     (CP_B * CP_L)   // 32768 tokens
#define CP_CHUNK  512
#define CP_NCHUNK (CP_L / CP_CHUNK)        // 16
#define CP_NCHTOT (CP_BL / CP_CHUNK)       // 64

// Scratch (static device globals)
__device__ float4 g_gates[CP_BL];
__device__ float4 g_scan[CP_BL];
__device__ float4 g_agg[CP_NCHTOT];
__device__ float2 g_pre[CP_NCHTOT];
__device__ int    g_sync;                                   // zero-initialized
__device__ __align__(16) __nv_bfloat16 g_Bhi[CP_D * CP_E];  // [n][k], K-major 128B rows
__device__ __align__(16) __nv_bfloat16 g_Blo[CP_D * CP_E];

__device__ __forceinline__ float4 comb(float4 l, float4 r) {
    float4 o;
    o.x = r.x * l.x;  o.y = fmaf(r.x, l.y, r.y);
    o.z = r.z * l.z;  o.w = fmaf(r.z, l.w, r.w);
    return o;
}

// ---------------- helpers (sm_103 base-target only: no tcgen05) ----------------
__device__ __forceinline__ uint32_t smem_u32(const void* p) {
    uint32_t a;
    asm("{ .reg .u64 t; cvta.to.shared.u64 t, %1; cvt.u32.u64 %0, t; }" : "=r"(a) : "l"(p));
    return a;
}
__device__ __forceinline__ uint32_t swz(uint32_t off) {   // SW128 swizzle (128B rows)
    return off ^ ((off >> 3) & 0x70);
}
__device__ __forceinline__ void ldsm4(uint32_t& r0, uint32_t& r1, uint32_t& r2, uint32_t& r3,
                                      uint32_t addr) {
    asm volatile("ldmatrix.sync.aligned.m8n8.x4.shared.b16 {%0,%1,%2,%3}, [%4];"
                 : "=r"(r0), "=r"(r1), "=r"(r2), "=r"(r3) : "r"(addr));
}
__device__ __forceinline__ void mma16816(float* c, const uint32_t* a, uint32_t b0, uint32_t b1) {
    asm volatile("mma.sync.aligned.m16n8k16.row.col.f32.bf16.bf16.f32 "
                 "{%0,%1,%2,%3}, {%4,%5,%6,%7}, {%8,%9}, {%0,%1,%2,%3};"
                 : "+f"(c[0]), "+f"(c[1]), "+f"(c[2]), "+f"(c[3])
                 : "r"(a[0]), "r"(a[1]), "r"(a[2]), "r"(a[3]), "r"(b0), "r"(b1));
}
__device__ __forceinline__ void cp16(uint32_t dst, const void* src) {
    asm volatile("cp.async.ca.shared.global [%0], [%1], 16;" :: "r"(dst), "l"(src));
}
__device__ __forceinline__ void cp_commit() {
    asm volatile("cp.async.commit_group;" ::: "memory");
}
template <int N>
__device__ __forceinline__ void cp_wait() {
    asm volatile("cp.async.wait_group %0;" :: "n"(N) : "memory");
}
__device__ __forceinline__ void pdl_trigger() {
    asm volatile("griddepcontrol.launch_dependents;" ::: "memory");
}
__device__ __forceinline__ void pdl_wait() {
    asm volatile("griddepcontrol.wait;" ::: "memory");
}

// ---------------------------------------------------------------------------
// Kernel 1: gate projections (+ fused read_w hi/lo split). R12 form.
// 2048 blocks x 256 threads; warp = 2 tokens.
// ---------------------------------------------------------------------------
__global__ __launch_bounds__(256) void gates_kernel(
    const float* __restrict__ x,
    const float* __restrict__ inc_w, const float* __restrict__ inc_b,
    const float* __restrict__ reset_w, const float* __restrict__ reset_b,
    const float* __restrict__ read_w,
    float* __restrict__ out_inc_logits)
{
    __shared__ __align__(16) float sI0[CP_D], sI1[CP_D], sR0[CP_D], sR1[CP_D];
    int tid = threadIdx.x;

    // ---- fused prep: this block's 32 elements of read_w hi/lo split ----
    if (tid < 32) {
        int idx = blockIdx.x * 32 + tid;    // 0..65535
        int n = idx >> 6, k = idx & 63;
        float v = read_w[k * CP_D + n];
        __nv_bfloat16 h = __float2bfloat16(v);
        float res = v - __bfloat162float(h);
        g_Bhi[n * CP_E + k] = h;
        g_Blo[n * CP_E + k] = __float2bfloat16(res);
    }

    for (int d = tid; d < CP_D; d += 256) {
        sI0[d] = inc_w[2 * d];     sI1[d] = inc_w[2 * d + 1];
        sR0[d] = reset_w[2 * d];   sR1[d] = reset_w[2 * d + 1];
    }
    __syncthreads();

    int lane = tid & 31;
    int wid  = tid >> 5;
    int tokA = blockIdx.x * 16 + wid * 2;
    int tokB = tokA + 1;

    const float4* xA = reinterpret_cast<const float4*>(x + (size_t)tokA * CP_D);
    const float4* xB = reinterpret_cast<const float4*>(x + (size_t)tokB * CP_D);
    const float4* wI0 = reinterpret_cast<const float4*>(sI0);
    const float4* wI1 = reinterpret_cast<const float4*>(sI1);
    const float4* wR0 = reinterpret_cast<const float4*>(sR0);
    const float4* wR1 = reinterpret_cast<const float4*>(sR1);

    float a0 = 0.f, a1 = 0.f, a2 = 0.f, a3 = 0.f;
    float b0 = 0.f, b1 = 0.f, b2 = 0.f, b3 = 0.f;
#pragma unroll
    for (int i = 0; i < 8; ++i) {
        int i4 = lane + (i << 5);
        float4 xa = __ldcs(&xA[i4]);
        float4 xb = __ldcs(&xB[i4]);
        float4 u = wI0[i4], v = wI1[i4], p = wR0[i4], q = wR1[i4];
        a0 = fmaf(xa.x, u.x, a0); a0 = fmaf(xa.y, u.y, a0);
        a0 = fmaf(xa.z, u.z, a0); a0 = fmaf(xa.w, u.w, a0);
        a1 = fmaf(xa.x, v.x, a1); a1 = fmaf(xa.y, v.y, a1);
        a1 = fmaf(xa.z, v.z, a1); a1 = fmaf(xa.w, v.w, a1);
        a2 = fmaf(xa.x, p.x, a2); a2 = fmaf(xa.y, p.y, a2);
        a2 = fmaf(xa.z, p.z, a2); a2 = fmaf(xa.w, p.w, a2);
        a3 = fmaf(xa.x, q.x, a3); a3 = fmaf(xa.y, q.y, a3);
        a3 = fmaf(xa.z, q.z, a3); a3 = fmaf(xa.w, q.w, a3);
        b0 = fmaf(xb.x, u.x, b0); b0 = fmaf(xb.y, u.y, b0);
        b0 = fmaf(xb.z, u.z, b0); b0 = fmaf(xb.w, u.w, b0);
        b1 = fmaf(xb.x, v.x, b1); b1 = fmaf(xb.y, v.y, b1);
        b1 = fmaf(xb.z, v.z, b1); b1 = fmaf(xb.w, v.w, b1);
        b2 = fmaf(xb.x, p.x, b2); b2 = fmaf(xb.y, p.y, b2);
        b2 = fmaf(xb.z, p.z, b2); b2 = fmaf(xb.w, p.w, b2);
        b3 = fmaf(xb.x, q.x, b3); b3 = fmaf(xb.y, q.y, b3);
        b3 = fmaf(xb.z, q.z, b3); b3 = fmaf(xb.w, q.w, b3);
    }
#pragma unroll
    for (int off = 16; off > 0; off >>= 1) {
        a0 += __shfl_xor_sync(0xffffffffu, a0, off);
        a1 += __shfl_xor_sync(0xffffffffu, a1, off);
        a2 += __shfl_xor_sync(0xffffffffu, a2, off);
        a3 += __shfl_xor_sync(0xffffffffu, a3, off);
        b0 += __shfl_xor_sync(0xffffffffu, b0, off);
        b1 += __shfl_xor_sync(0xffffffffu, b1, off);
        b2 += __shfl_xor_sync(0xffffffffu, b2, off);
        b3 += __shfl_xor_sync(0xffffffffu, b3, off);
    }
    if (lane == 0) {
        float ib0 = inc_b[0], ib1 = inc_b[1], rb0 = reset_b[0], rb1 = reset_b[1];
        float ilA0 = a0 + ib0, ilA1 = a1 + ib1;
        float rlA0 = a2 + rb0, rlA1 = a3 + rb1;
        reinterpret_cast<float2*>(out_inc_logits)[tokA] = make_float2(ilA0, ilA1);
        g_gates[tokA] = make_float4(1.f / (1.f + expf(rlA0)),
                                    1.f / (1.f + expf(-ilA0)),
                                    1.f / (1.f + expf(rlA1)),
                                    1.f / (1.f + expf(-ilA1)));
        float ilB0 = b0 + ib0, ilB1 = b1 + ib1;
        float rlB0 = b2 + rb0, rlB1 = b3 + rb1;
        reinterpret_cast<float2*>(out_inc_logits)[tokB] = make_float2(ilB0, ilB1);
        g_gates[tokB] = make_float4(1.f / (1.f + expf(rlB0)),
                                    1.f / (1.f + expf(-ilB0)),
                                    1.f / (1.f + expf(rlB1)),
                                    1.f / (1.f + expf(-ilB1)));
    }
}

// ---------------------------------------------------------------------------
// Kernel 2: per-chunk inclusive scan + fused aggregate scan in the tail.
// Triggers dependent (readout) launch early — readout preamble overlaps.
// ---------------------------------------------------------------------------
__global__ __launch_bounds__(256) void chunkscan_kernel()
{
    __shared__ float4 wagg[8];
    __shared__ float4 wexc[8];
    __shared__ int s_last;
    int t = threadIdx.x, lane = t & 31, wid = t >> 5;
    int tok = blockIdx.x * CP_CHUNK + 2 * t;

    pdl_trigger();   // readout may begin its scan-independent preamble

    float4 a = g_gates[tok];
    float4 b = g_gates[tok + 1];
    float4 s = comb(a, b);

#pragma unroll
    for (int off = 1; off < 32; off <<= 1) {
        float4 l;
        l.x = __shfl_up_sync(0xffffffffu, s.x, off);
        l.y = __shfl_up_sync(0xffffffffu, s.y, off);
        l.z = __shfl_up_sync(0xffffffffu, s.z, off);
        l.w = __shfl_up_sync(0xffffffffu, s.w, off);
        if (lane >= off) s = comb(l, s);
    }
    if (lane == 31) wagg[wid] = s;
    __syncthreads();

    if (wid == 0) {
        float4 v = (lane < 8) ? wagg[lane] : make_float4(1.f, 0.f, 1.f, 0.f);
#pragma unroll
        for (int off = 1; off < 8; off <<= 1) {
            float4 l;
            l.x = __shfl_up_sync(0xffffffffu, v.x, off);
            l.y = __shfl_up_sync(0xffffffffu, v.y, off);
            l.z = __shfl_up_sync(0xffffffffu, v.z, off);
            l.w = __shfl_up_sync(0xffffffffu, v.w, off);
            if (lane >= off && lane < 8) v = comb(l, v);
        }
        if (lane == 0) wexc[0] = make_float4(1.f, 0.f, 1.f, 0.f);
        if (lane < 7)  wexc[lane + 1] = v;
    }
    __syncthreads();

    float4 se;
    {
        float4 l;
        l.x = __shfl_up_sync(0xffffffffu, s.x, 1);
        l.y = __shfl_up_sync(0xffffffffu, s.y, 1);
        l.z = __shfl_up_sync(0xffffffffu, s.z, 1);
        l.w = __shfl_up_sync(0xffffffffu, s.w, 1);
        se = (lane == 0) ? make_float4(1.f, 0.f, 1.f, 0.f) : l;
    }
    float4 P = comb(wexc[wid], se);
    float4 o0 = comb(P, a);
    float4 o1 = comb(o0, b);
    g_scan[tok]     = o0;
    g_scan[tok + 1] = o1;
    if (t == 255) g_agg[blockIdx.x] = o1;

    __threadfence();
    __syncthreads();
    if (t == 0) {
        int prev = atomicAdd(&g_sync, 1);
        s_last = (prev == CP_NCHTOT - 1);
    }
    __syncthreads();
    if (s_last) {
        if (t < CP_B) {
            float c0 = 0.f, c1 = 0.f;
            for (int j = 0; j < CP_NCHUNK; ++j) {
                g_pre[t * CP_NCHUNK + j] = make_float2(c0, c1);
                float4 ag = g_agg[t * CP_NCHUNK + j];
                c0 = fmaf(ag.x, c0, ag.y);
                c1 = fmaf(ag.z, c1, ag.w);
            }
        }
        if (t == 0) g_sync = 0;
    }
}

// ---------------------------------------------------------------------------
// Kernel 3: counters + embedding + mma.sync bf16x3 GEMM + bias (R12 form),
// launched with PDL: bias + B-chunk-0 staging run before griddepcontrol.wait.
// ---------------------------------------------------------------------------
#define SMB_BIAS  0
#define SMB_EHI   4096
#define SMB_ELO   20480
#define SMB_B     36864
#define SMB_BUF   16384
#define SM_TOT    (SMB_B + 2 * SMB_BUF)   // 69632

__device__ __forceinline__ void stage_B(uint32_t sb, int nt, int buf, int tid)
{
    const char* srcH = (const char*)g_Bhi + (size_t)nt * 64 * 128;
    const char* srcL = (const char*)g_Blo + (size_t)nt * 64 * 128;
    uint32_t dstH = sb + SMB_B + buf * SMB_BUF;
    uint32_t dstL = dstH + 8192;
#pragma unroll
    for (int m = 0; m < 2; ++m) {
        int idx = tid + m * 256;          // 0..511
        int nl = idx >> 3, c16 = idx & 7;
        uint32_t sw = swz((uint32_t)(nl * 128 + c16 * 16));
        cp16(dstH + sw, srcH + nl * 128 + c16 * 16);
        cp16(dstL + sw, srcL + nl * 128 + c16 * 16);
    }
}

__global__ __launch_bounds__(256, 2) void readout_kernel(
    const float* __restrict__ read_b,
    float* __restrict__ out_inj,        // (B*L, 1024)
    float* __restrict__ out_counters)   // (B*L, 2)
{
    extern __shared__ __align__(1024) char smem[];
    uint32_t sb = smem_u32(smem);
    int tid = threadIdx.x, lane = tid & 31, w = tid >> 5;
    int wy = w >> 1, wx = w & 1;        // 4 m-groups x 2 n-groups
    int tok0 = blockIdx.x * 128;

    // ---- scan-independent preamble (overlaps chunkscan via PDL) ----
    reinterpret_cast<float4*>(smem + SMB_BIAS)[tid] =
        reinterpret_cast<const float4*>(read_b)[tid];
    stage_B(sb, 0, 0, tid);       // g_Bhi/g_Blo written by gates_kernel (done)
    cp_commit();

    pdl_wait();   // chunkscan fully complete; g_scan/g_pre visible

    // ---- counters + embedding -> bf16 hi/lo swizzled tiles [128 x 64] ----
    {
        int t   = tid >> 1;
        int k   = tid & 1;
        int tok = tok0 + t;
        int b   = tok / CP_L;
        int jc  = (tok % CP_L) / CP_CHUNK;
        float2 pre = g_pre[b * CP_NCHUNK + jc];
        float4 sc  = g_scan[tok];
        float pk = k ? sc.z : sc.x;
        float pi = k ? sc.w : sc.y;
        float pp = k ? pre.y : pre.x;
        float c  = fmaf(pk, pp, pi);
        out_counters[tok * 2 + k] = c;

        float sv[16], cv[16];
#pragma unroll
        for (int f = 0; f < CP_NF; ++f) {
            float invf = exp2f(-12.0f * (float)f / 15.0f);
            sincosf(c * invf, &sv[f], &cv[f]);
        }
#pragma unroll
        for (int q = 0; q < 8; ++q) {
            unsigned long long hi = 0ull, lo = 0ull;
#pragma unroll
            for (int bq = 0; bq < 4; ++bq) {
                int j = 4 * q + bq;
                float v = (j < 16) ? sv[j] : cv[j - 16];
                __nv_bfloat16 h = __float2bfloat16(v);
                float res = v - __bfloat162float(h);
                __nv_bfloat16 l = __float2bfloat16(res);
                hi |= (unsigned long long)__bfloat16_as_ushort(h) << (16 * bq);
                lo |= (unsigned long long)__bfloat16_as_ushort(l) << (16 * bq);
            }
            uint32_t off = (uint32_t)(t * 128 + k * 64 + q * 8);
            uint32_t sw = swz(off);
            *reinterpret_cast<unsigned long long*>(smem + SMB_EHI + sw) = hi;
            *reinterpret_cast<unsigned long long*>(smem + SMB_ELO + sw) = lo;
        }
    }

    __syncthreads();   // emb tiles complete (never modified again)

    int row = lane >> 2, tcol = 2 * (lane & 3);
    int mlsb = lane >> 3, r8 = lane & 7;

    // ---- A fragments register-resident ----
    uint32_t ah[4][2][4], al[4][2][4];
#pragma unroll
    for (int kk = 0; kk < 4; ++kk)
#pragma unroll
        for (int mt = 0; mt < 2; ++mt) {
            uint32_t aoff = swz((uint32_t)((wy * 32 + mt * 16 + (mlsb & 1) * 8 + r8) * 128 +
                                           (2 * kk + (mlsb >> 1)) * 16));
            ldsm4(ah[kk][mt][0], ah[kk][mt][1], ah[kk][mt][2], ah[kk][mt][3],
                  sb + SMB_EHI + aoff);
            ldsm4(al[kk][mt][0], al[kk][mt][1], al[kk][mt][2], al[kk][mt][3],
                  sb + SMB_ELO + aoff);
        }

#pragma unroll 1
    for (int nt = 0; nt < 16; ++nt) {
        int buf = nt & 1;
        if (nt < 15) {
            stage_B(sb, nt + 1, buf ^ 1, tid);
            cp_commit();
            cp_wait<1>();
        } else {
            cp_wait<0>();
        }
        __syncthreads();

        uint32_t bbase = sb + SMB_B + buf * SMB_BUF;
        float acc[2][4][4];
#pragma unroll
        for (int mt = 0; mt < 2; ++mt)
#pragma unroll
            for (int p = 0; p < 4; ++p)
#pragma unroll
                for (int q = 0; q < 4; ++q) acc[mt][p][q] = 0.f;

#pragma unroll
        for (int kk = 0; kk < 4; ++kk) {
#pragma unroll
            for (int p4 = 0; p4 < 2; ++p4) {
                int pg = wx * 2 + p4;
                uint32_t bh[4], bl[4];
                uint32_t boff = swz((uint32_t)((pg * 16 + (mlsb >> 1) * 8 + r8) * 128 +
                                               (2 * kk + (mlsb & 1)) * 16));
                ldsm4(bh[0], bh[1], bh[2], bh[3], bbase + boff);
                ldsm4(bl[0], bl[1], bl[2], bl[3], bbase + 8192 + boff);
#pragma unroll
                for (int mt = 0; mt < 2; ++mt) {
                    mma16816(acc[mt][2 * p4],     ah[kk][mt], bh[0], bh[1]);
                    mma16816(acc[mt][2 * p4 + 1], ah[kk][mt], bh[2], bh[3]);
                    mma16816(acc[mt][2 * p4],     ah[kk][mt], bl[0], bl[1]);
                    mma16816(acc[mt][2 * p4 + 1], ah[kk][mt], bl[2], bl[3]);
                    mma16816(acc[mt][2 * p4],     al[kk][mt], bh[0], bh[1]);
                    mma16816(acc[mt][2 * p4 + 1], al[kk][mt], bh[2], bh[3]);
                }
            }
        }

        // epilogue: +bias, streaming stores; warp = 32 tokens x 32 cols
        const float* sbias = reinterpret_cast<const float*>(smem + SMB_BIAS) +
                             nt * 64 + wx * 32;
#pragma unroll
        for (int mt = 0; mt < 2; ++mt) {
            float* o0 = out_inj + (size_t)(tok0 + wy * 32 + mt * 16 + row) * CP_D +
                        nt * 64 + wx * 32;
            float* o1 = o0 + 8 * CP_D;
#pragma unroll
            for (int p = 0; p < 4; ++p) {
                int col = p * 8 + tcol;
                float2 bv = *reinterpret_cast<const float2*>(sbias + col);
                __stcs(reinterpret_cast<float2*>(o0 + col),
                       make_float2(acc[mt][p][0] + bv.x, acc[mt][p][1] + bv.y));
                __stcs(reinterpret_cast<float2*>(o1 + col),
                       make_float2(acc[mt][p][2] + bv.x, acc[mt][p][3] + bv.y));
            }
        }
        __syncthreads();
    }
}

// ---------------------------------------------------------------------------
// Launch: THREE kernels, chunkscan->readout edge uses PDL.
// ---------------------------------------------------------------------------
extern "C" void kernel_launch(void* const* d_in, const int* in_sizes, int n_in,
                              void* d_out, int out_size)
{
    const float* x       = (const float*)d_in[0];
    const float* inc_w   = (const float*)d_in[1];
    const float* inc_b   = (const float*)d_in[2];
    const float* reset_w = (const float*)d_in[3];
    const float* reset_b = (const float*)d_in[4];
    const float* read_w  = (const float*)d_in[5];
    const float* read_b  = (const float*)d_in[6];

    float* out        = (float*)d_out;
    float* out_inj    = out;
    float* out_inclog = out + (size_t)CP_BL * CP_D;
    float* out_cnt    = out_inclog + (size_t)CP_BL * CP_K;

    cudaFuncSetAttribute(readout_kernel,
                         cudaFuncAttributeMaxDynamicSharedMemorySize, SM_TOT);

    gates_kernel<<<CP_BL / 16, 256>>>(x, inc_w, inc_b, reset_w, reset_b,
                                      read_w, out_inclog);
    chunkscan_kernel<<<CP_NCHTOT, 256>>>();

    cudaLaunchConfig_t cfg = {};
    cfg.gridDim = dim3(CP_BL / 128);
    cfg.blockDim = dim3(256);
    cfg.dynamicSmemBytes = SM_TOT;
    cfg.stream = 0;
    cudaLaunchAttribute at[1];
    at[0].id = cudaLaunchAttributeProgrammaticStreamSerialization;
    at[0].val.programmaticStreamSerializationAllowed = 1;
    cfg.attrs = at;
    cfg.numAttrs = 1;
    cudaLaunchKernelEx(&cfg, readout_kernel, read_b, out_inj, out_cnt);
}